// round 1
// baseline (speedup 1.0000x reference)
#include <cuda_runtime.h>
#include <cuda_bf16.h>
#include <mma.h>

using namespace nvcuda;

// Problem constants
#define B_SZ 4
#define T_SZ 2048
#define D_SZ 1024
__device__ __constant__ float kScale = 0.03125f; // 1/sqrt(1024)

// Scratch (device globals: allocation-free per harness rules)
__device__ float g_Q[B_SZ * T_SZ * D_SZ];   // 32 MB
__device__ float g_K[B_SZ * T_SZ * D_SZ];   // 32 MB
__device__ float g_V[B_SZ * T_SZ * D_SZ];   // 32 MB
__device__ float g_S[B_SZ * T_SZ * T_SZ];   // 64 MB (raw scores)
__device__ float g_P[B_SZ * T_SZ * T_SZ];   // 64 MB (softmax weights)

// ---------------------------------------------------------------------------
// TF32 WMMA GEMM: C[M,N] = A[M,K] * B  (B row-major [K,N] or "NT": B=[N,K])
// Block tile 128x128x32, 8 warps (4x2), warp tile 32x64, m16n16k8 frags.
// TRANSB : B is [N,K] row-major, used as B^T (scores = Q K^T)
// CSKIP  : skip 128x128 blocks strictly above the causal diagonal
// KLIM   : limit K-loop to (bm+1)*BM (PV gemm: P[t][s]=0 for s>t)
// ---------------------------------------------------------------------------
constexpr int BM = 128, BN = 128, BK = 32;

template <bool TRANSB, bool CSKIP, bool KLIM>
__global__ __launch_bounds__(256) void gemm_tf32(
    const float* __restrict__ A, const float* __restrict__ Bm,
    float* __restrict__ C, int N, int K,
    size_t sA, size_t sB, size_t sC)
{
    const int bm = blockIdx.y, bn = blockIdx.x, bz = blockIdx.z;
    if (CSKIP && bn > bm) return;

    A  += (size_t)bz * sA;
    Bm += (size_t)bz * sB;
    C  += (size_t)bz * sC;

    __shared__ float As[BM][BK + 4];
    constexpr int BR = TRANSB ? BN : BK;
    constexpr int BC = TRANSB ? (BK + 4) : (BN + 4);
    __shared__ float Bs[BR][BC];

    const int tid  = threadIdx.x;
    const int warp = tid >> 5;
    const int wrow = (warp & 3) * 32;   // warp M offset within block
    const int wcol = (warp >> 2) * 64;  // warp N offset within block

    wmma::fragment<wmma::accumulator, 16, 16, 8, float> acc[2][4];
    #pragma unroll
    for (int i = 0; i < 2; i++)
        #pragma unroll
        for (int j = 0; j < 4; j++) wmma::fill_fragment(acc[i][j], 0.0f);

    const int nk = KLIM ? ((bm + 1) * BM) / BK : K / BK;

    // A / B(NT) staging: 32-float rows -> 8 threads/row (float4 each), 32 rows/pass
    const int ar = tid >> 3;
    const int ac = (tid & 7) * 4;
    // B(NN) staging: 128-float rows -> 32 threads/row, 8 rows/pass
    const int br = tid >> 5;
    const int bc = (tid & 31) * 4;

    for (int kt = 0; kt < nk; kt++) {
        const int k0 = kt * BK;

        #pragma unroll
        for (int p = 0; p < 4; p++) {
            const float4 v = *reinterpret_cast<const float4*>(
                &A[(size_t)(bm * BM + p * 32 + ar) * K + k0 + ac]);
            As[p * 32 + ar][ac + 0] = wmma::__float_to_tf32(v.x);
            As[p * 32 + ar][ac + 1] = wmma::__float_to_tf32(v.y);
            As[p * 32 + ar][ac + 2] = wmma::__float_to_tf32(v.z);
            As[p * 32 + ar][ac + 3] = wmma::__float_to_tf32(v.w);
        }
        if (TRANSB) {
            #pragma unroll
            for (int p = 0; p < 4; p++) {
                const float4 v = *reinterpret_cast<const float4*>(
                    &Bm[(size_t)(bn * BN + p * 32 + ar) * K + k0 + ac]);
                Bs[p * 32 + ar][ac + 0] = wmma::__float_to_tf32(v.x);
                Bs[p * 32 + ar][ac + 1] = wmma::__float_to_tf32(v.y);
                Bs[p * 32 + ar][ac + 2] = wmma::__float_to_tf32(v.z);
                Bs[p * 32 + ar][ac + 3] = wmma::__float_to_tf32(v.w);
            }
        } else {
            #pragma unroll
            for (int p = 0; p < 4; p++) {
                const float4 v = *reinterpret_cast<const float4*>(
                    &Bm[(size_t)(k0 + p * 8 + br) * N + bn * BN + bc]);
                Bs[p * 8 + br][bc + 0] = wmma::__float_to_tf32(v.x);
                Bs[p * 8 + br][bc + 1] = wmma::__float_to_tf32(v.y);
                Bs[p * 8 + br][bc + 2] = wmma::__float_to_tf32(v.z);
                Bs[p * 8 + br][bc + 3] = wmma::__float_to_tf32(v.w);
            }
        }
        __syncthreads();

        #pragma unroll
        for (int kk = 0; kk < BK / 8; kk++) {
            wmma::fragment<wmma::matrix_a, 16, 16, 8, wmma::precision::tf32,
                           wmma::row_major> af[2];
            #pragma unroll
            for (int i = 0; i < 2; i++)
                wmma::load_matrix_sync(af[i], &As[wrow + i * 16][kk * 8], BK + 4);

            if constexpr (TRANSB) {
                wmma::fragment<wmma::matrix_b, 16, 16, 8, wmma::precision::tf32,
                               wmma::col_major> bf[4];
                #pragma unroll
                for (int j = 0; j < 4; j++)
                    wmma::load_matrix_sync(bf[j], &Bs[wcol + j * 16][kk * 8], BK + 4);
                #pragma unroll
                for (int i = 0; i < 2; i++)
                    #pragma unroll
                    for (int j = 0; j < 4; j++)
                        wmma::mma_sync(acc[i][j], af[i], bf[j], acc[i][j]);
            } else {
                wmma::fragment<wmma::matrix_b, 16, 16, 8, wmma::precision::tf32,
                               wmma::row_major> bf[4];
                #pragma unroll
                for (int j = 0; j < 4; j++)
                    wmma::load_matrix_sync(bf[j], &Bs[kk * 8][wcol + j * 16], BN + 4);
                #pragma unroll
                for (int i = 0; i < 2; i++)
                    #pragma unroll
                    for (int j = 0; j < 4; j++)
                        wmma::mma_sync(acc[i][j], af[i], bf[j], acc[i][j]);
            }
        }
        __syncthreads();
    }

    #pragma unroll
    for (int i = 0; i < 2; i++)
        #pragma unroll
        for (int j = 0; j < 4; j++)
            wmma::store_matrix_sync(
                &C[(size_t)(bm * BM + wrow + i * 16) * N + bn * BN + wcol + j * 16],
                acc[i][j], N, wmma::mem_row_major);
}

// ---------------------------------------------------------------------------
// Row softmax with causal mask + scale fused. One block per (b,t) row.
// 256 threads x 8 cols each = 2048. Masked cols produce exact 0.
// ---------------------------------------------------------------------------
__global__ __launch_bounds__(256) void softmax_causal(
    const float* __restrict__ S, float* __restrict__ P)
{
    const int row = blockIdx.x;          // 0 .. B*T-1
    const int t   = row & (T_SZ - 1);
    const size_t base = (size_t)row * T_SZ;
    const int tid = threadIdx.x;

    float e[8];
    float m = -1e30f;
    #pragma unroll
    for (int i = 0; i < 8; i++) {
        const int j = tid + i * 256;
        const float v = (j <= t) ? S[base + j] * kScale : -1e30f;
        e[i] = v;
        m = fmaxf(m, v);
    }

    __shared__ float shm[8], shs[8];
    #pragma unroll
    for (int o = 16; o; o >>= 1) m = fmaxf(m, __shfl_xor_sync(0xffffffffu, m, o));
    if ((tid & 31) == 0) shm[tid >> 5] = m;
    __syncthreads();
    float mfin = shm[0];
    #pragma unroll
    for (int i = 1; i < 8; i++) mfin = fmaxf(mfin, shm[i]);

    float s = 0.0f;
    #pragma unroll
    for (int i = 0; i < 8; i++) {
        e[i] = __expf(e[i] - mfin);   // masked -> exp(-1e30) == 0
        s += e[i];
    }
    #pragma unroll
    for (int o = 16; o; o >>= 1) s += __shfl_xor_sync(0xffffffffu, s, o);
    if ((tid & 31) == 0) shs[tid >> 5] = s;
    __syncthreads();
    float sfin = 0.0f;
    #pragma unroll
    for (int i = 0; i < 8; i++) sfin += shs[i];

    const float inv = 1.0f / sfin;
    #pragma unroll
    for (int i = 0; i < 8; i++)
        P[base + tid + i * 256] = e[i] * inv;
}

// ---------------------------------------------------------------------------
extern "C" void kernel_launch(void* const* d_in, const int* in_sizes, int n_in,
                              void* d_out, int out_size)
{
    (void)in_sizes; (void)n_in; (void)out_size;
    const float* X  = (const float*)d_in[0];
    const float* Wq = (const float*)d_in[1];
    const float* Wk = (const float*)d_in[2];
    const float* Wv = (const float*)d_in[3];
    float* out = (float*)d_out;

    float *Q, *K, *V, *S, *P;
    cudaGetSymbolAddress((void**)&Q, g_Q);
    cudaGetSymbolAddress((void**)&K, g_K);
    cudaGetSymbolAddress((void**)&V, g_V);
    cudaGetSymbolAddress((void**)&S, g_S);
    cudaGetSymbolAddress((void**)&P, g_P);

    const dim3 blk(256, 1, 1);
    const size_t sQK = (size_t)T_SZ * D_SZ;   // per-batch Q/K/V stride
    const size_t sS  = (size_t)T_SZ * T_SZ;   // per-batch S/P stride

    // QKV projections: [8192,1024] x [1024,1024] (NN), all batches fused in M
    gemm_tf32<false, false, false><<<dim3(D_SZ / BN, (B_SZ * T_SZ) / BM, 1), blk>>>(
        X, Wq, Q, D_SZ, D_SZ, 0, 0, 0);
    gemm_tf32<false, false, false><<<dim3(D_SZ / BN, (B_SZ * T_SZ) / BM, 1), blk>>>(
        X, Wk, K, D_SZ, D_SZ, 0, 0, 0);
    gemm_tf32<false, false, false><<<dim3(D_SZ / BN, (B_SZ * T_SZ) / BM, 1), blk>>>(
        X, Wv, V, D_SZ, D_SZ, 0, 0, 0);

    // Scores: S = Q K^T per batch (NT), causal upper blocks skipped
    gemm_tf32<true, true, false><<<dim3(T_SZ / BN, T_SZ / BM, B_SZ), blk>>>(
        Q, K, S, T_SZ, D_SZ, sQK, sQK, sS);

    // Softmax (scale + causal mask fused)
    softmax_causal<<<B_SZ * T_SZ, 256>>>(S, P);

    // Output: O = P V per batch (NN), K-loop causally limited
    gemm_tf32<false, false, true><<<dim3(D_SZ / BN, T_SZ / BM, B_SZ), blk>>>(
        P, V, out, D_SZ, T_SZ, sS, sQK, sQK);
}

// round 4
// speedup vs baseline: 1.1654x; 1.1654x over previous
#include <cuda_runtime.h>
#include <cuda_bf16.h>
#include <cstdint>
#include <mma.h>

using namespace nvcuda;

#define B_SZ 4
#define T_SZ 2048
#define D_SZ 1024
__device__ __constant__ float kScale = 0.03125f; // 1/sqrt(1024)

// Scratch (device globals: allocation-free per harness rules)
__device__ float g_X[B_SZ * T_SZ * D_SZ];       // X rounded to tf32
__device__ float g_W[3 * D_SZ * D_SZ];          // Wq|Wk|Wv rounded to tf32
__device__ float g_Q[B_SZ * T_SZ * D_SZ];
__device__ float g_K[B_SZ * T_SZ * D_SZ];
__device__ float g_V[B_SZ * T_SZ * D_SZ];
__device__ float g_S[B_SZ * T_SZ * T_SZ];
__device__ float g_P[B_SZ * T_SZ * T_SZ];

// ---------------------------------------------------------------------------
// cp.async helpers
// ---------------------------------------------------------------------------
__device__ __forceinline__ void cp_async16(void* smem_dst, const void* gsrc) {
    unsigned s = (unsigned)__cvta_generic_to_shared(smem_dst);
    asm volatile("cp.async.cg.shared.global [%0], [%1], 16;" :: "r"(s), "l"(gsrc));
}
__device__ __forceinline__ void cp_commit() {
    asm volatile("cp.async.commit_group;");
}
template <int N>
__device__ __forceinline__ void cp_wait() {
    asm volatile("cp.async.wait_group %0;" :: "n"(N));
}

// ---------------------------------------------------------------------------
// TF32 WMMA GEMM, 2-stage cp.async pipeline.
// Block 128x128x32, 8 warps (4x2), warp tile 32x64.
// All operands are PRE-ROUNDED to tf32, so raw HMMA truncation is exact.
// TRANSB: B=[N,K] used as B^T. CSKIP: skip causal-upper blocks.
// KLIM: K-loop limited to (bm+1)*BM. CVT: round C to tf32 on store.
// ---------------------------------------------------------------------------
constexpr int BM = 128, BN = 128, BK = 32;
constexpr int AS_STR = BK + 4;  // 36

// Host-side smem sizes (bytes): 2 stages of (A tile + B tile)
constexpr int SMEM_NN = 2 * (BM * AS_STR + BK * (BN + 4)) * 4;  // NN: B tile [BK][BN+4]
constexpr int SMEM_NT = 2 * (BM * AS_STR + BN * (BK + 4)) * 4;  // NT: B tile [BN][BK+4]

template <bool TRANSB, bool CSKIP, bool KLIM, bool CVT>
__global__ __launch_bounds__(256) void gemm_tf32(
    const float* __restrict__ A, const float* __restrict__ Bm,
    float* __restrict__ C, int N, int K,
    size_t sA, size_t sB, size_t sC)
{
    const int bm = blockIdx.y, bn = blockIdx.x, bz = blockIdx.z;
    if (CSKIP && bn > bm) return;
    A  += (size_t)bz * sA;
    Bm += (size_t)bz * sB;
    C  += (size_t)bz * sC;

    constexpr int BROWS = TRANSB ? BN : BK;
    constexpr int BSTR  = TRANSB ? (BK + 4) : (BN + 4);

    extern __shared__ float sm[];
    float* AsBase = sm;                       // [2][BM][AS_STR]
    float* BsBase = sm + 2 * BM * AS_STR;     // [2][BROWS][BSTR]

    const int tid  = threadIdx.x;
    const int warp = tid >> 5;
    const int wrow = (warp & 3) * 32;
    const int wcol = (warp >> 2) * 64;

    wmma::fragment<wmma::accumulator, 16, 16, 8, float> acc[2][4];
    #pragma unroll
    for (int i = 0; i < 2; i++)
        #pragma unroll
        for (int j = 0; j < 4; j++) wmma::fill_fragment(acc[i][j], 0.0f);

    const int nk = KLIM ? ((bm + 1) * BM) / BK : K / BK;

    const int ar = tid >> 3,  ac = (tid & 7) * 4;   // 32-wide rows
    const int br = tid >> 5,  bc = (tid & 31) * 4;  // 128-wide rows

    auto load_stage = [&](int kt, int st) {
        const int k0 = kt * BK;
        float* As = AsBase + st * BM * AS_STR;
        float* Bs = BsBase + st * BROWS * BSTR;
        #pragma unroll
        for (int p = 0; p < 4; p++)
            cp_async16(As + (p * 32 + ar) * AS_STR + ac,
                       A + (size_t)(bm * BM + p * 32 + ar) * K + k0 + ac);
        if (TRANSB) {
            #pragma unroll
            for (int p = 0; p < 4; p++)
                cp_async16(Bs + (p * 32 + ar) * BSTR + ac,
                           Bm + (size_t)(bn * BN + p * 32 + ar) * K + k0 + ac);
        } else {
            #pragma unroll
            for (int p = 0; p < 4; p++)
                cp_async16(Bs + (p * 8 + br) * BSTR + bc,
                           Bm + (size_t)(k0 + p * 8 + br) * N + bn * BN + bc);
        }
        cp_commit();
    };

    load_stage(0, 0);

    for (int kt = 0; kt < nk; kt++) {
        const int st = kt & 1;
        if (kt + 1 < nk) {
            load_stage(kt + 1, st ^ 1);
            cp_wait<1>();
        } else {
            cp_wait<0>();
        }
        __syncthreads();

        const float* As = AsBase + st * BM * AS_STR;
        const float* Bs = BsBase + st * BROWS * BSTR;

        #pragma unroll
        for (int kk = 0; kk < BK / 8; kk++) {
            wmma::fragment<wmma::matrix_a, 16, 16, 8, wmma::precision::tf32,
                           wmma::row_major> af[2];
            #pragma unroll
            for (int i = 0; i < 2; i++)
                wmma::load_matrix_sync(af[i], As + (wrow + i * 16) * AS_STR + kk * 8,
                                       AS_STR);
            if constexpr (TRANSB) {
                wmma::fragment<wmma::matrix_b, 16, 16, 8, wmma::precision::tf32,
                               wmma::col_major> bf[4];
                #pragma unroll
                for (int j = 0; j < 4; j++)
                    wmma::load_matrix_sync(bf[j], Bs + (wcol + j * 16) * BSTR + kk * 8,
                                           BSTR);
                #pragma unroll
                for (int i = 0; i < 2; i++)
                    #pragma unroll
                    for (int j = 0; j < 4; j++)
                        wmma::mma_sync(acc[i][j], af[i], bf[j], acc[i][j]);
            } else {
                wmma::fragment<wmma::matrix_b, 16, 16, 8, wmma::precision::tf32,
                               wmma::row_major> bf[4];
                #pragma unroll
                for (int j = 0; j < 4; j++)
                    wmma::load_matrix_sync(bf[j], Bs + (kk * 8) * BSTR + wcol + j * 16,
                                           BSTR);
                #pragma unroll
                for (int i = 0; i < 2; i++)
                    #pragma unroll
                    for (int j = 0; j < 4; j++)
                        wmma::mma_sync(acc[i][j], af[i], bf[j], acc[i][j]);
            }
        }
        __syncthreads();
    }

    #pragma unroll
    for (int i = 0; i < 2; i++)
        #pragma unroll
        for (int j = 0; j < 4; j++) {
            if (CVT) {
                #pragma unroll
                for (int e = 0; e < acc[i][j].num_elements; e++)
                    acc[i][j].x[e] = wmma::__float_to_tf32(acc[i][j].x[e]);
            }
            wmma::store_matrix_sync(
                &C[(size_t)(bm * BM + wrow + i * 16) * N + bn * BN + wcol + j * 16],
                acc[i][j], N, wmma::mem_row_major);
        }
}

// ---------------------------------------------------------------------------
// Elementwise round-to-tf32 (float4 vectorized)
// ---------------------------------------------------------------------------
__global__ void cvt_tf32(const float4* __restrict__ in, float4* __restrict__ out,
                         int n4)
{
    const int i = blockIdx.x * blockDim.x + threadIdx.x;
    if (i < n4) {
        float4 v = in[i];
        v.x = wmma::__float_to_tf32(v.x);
        v.y = wmma::__float_to_tf32(v.y);
        v.z = wmma::__float_to_tf32(v.z);
        v.w = wmma::__float_to_tf32(v.w);
        out[i] = v;
    }
}

// ---------------------------------------------------------------------------
// Row softmax: causal mask + scale fused, output rounded to tf32.
// ---------------------------------------------------------------------------
__global__ __launch_bounds__(256) void softmax_causal(
    const float* __restrict__ S, float* __restrict__ P)
{
    const int row = blockIdx.x;
    const int t   = row & (T_SZ - 1);
    const size_t base = (size_t)row * T_SZ;
    const int tid = threadIdx.x;

    float e[8];
    float m = -1e30f;
    #pragma unroll
    for (int i = 0; i < 8; i++) {
        const int j = tid + i * 256;
        const float v = (j <= t) ? S[base + j] * kScale : -1e30f;
        e[i] = v;
        m = fmaxf(m, v);
    }

    __shared__ float shm[8], shs[8];
    #pragma unroll
    for (int o = 16; o; o >>= 1) m = fmaxf(m, __shfl_xor_sync(0xffffffffu, m, o));
    if ((tid & 31) == 0) shm[tid >> 5] = m;
    __syncthreads();
    float mfin = shm[0];
    #pragma unroll
    for (int i = 1; i < 8; i++) mfin = fmaxf(mfin, shm[i]);

    float s = 0.0f;
    #pragma unroll
    for (int i = 0; i < 8; i++) {
        e[i] = __expf(e[i] - mfin);
        s += e[i];
    }
    #pragma unroll
    for (int o = 16; o; o >>= 1) s += __shfl_xor_sync(0xffffffffu, s, o);
    if ((tid & 31) == 0) shs[tid >> 5] = s;
    __syncthreads();
    float sfin = 0.0f;
    #pragma unroll
    for (int i = 0; i < 8; i++) sfin += shs[i];

    const float inv = 1.0f / sfin;
    #pragma unroll
    for (int i = 0; i < 8; i++)
        P[base + tid + i * 256] = wmma::__float_to_tf32(e[i] * inv);
}

// ---------------------------------------------------------------------------
extern "C" void kernel_launch(void* const* d_in, const int* in_sizes, int n_in,
                              void* d_out, int out_size)
{
    (void)in_sizes; (void)n_in; (void)out_size;
    const float* Xin = (const float*)d_in[0];
    const float* Wq  = (const float*)d_in[1];
    const float* Wk  = (const float*)d_in[2];
    const float* Wv  = (const float*)d_in[3];
    float* out = (float*)d_out;

    float *X, *W, *Q, *K, *V, *S, *P;
    cudaGetSymbolAddress((void**)&X, g_X);
    cudaGetSymbolAddress((void**)&W, g_W);
    cudaGetSymbolAddress((void**)&Q, g_Q);
    cudaGetSymbolAddress((void**)&K, g_K);
    cudaGetSymbolAddress((void**)&V, g_V);
    cudaGetSymbolAddress((void**)&S, g_S);
    cudaGetSymbolAddress((void**)&P, g_P);

    cudaFuncSetAttribute(gemm_tf32<false, false, false, true>,
                         cudaFuncAttributeMaxDynamicSharedMemorySize, SMEM_NN);
    cudaFuncSetAttribute(gemm_tf32<true, true, false, false>,
                         cudaFuncAttributeMaxDynamicSharedMemorySize, SMEM_NT);
    cudaFuncSetAttribute(gemm_tf32<false, false, true, false>,
                         cudaFuncAttributeMaxDynamicSharedMemorySize, SMEM_NN);

    const dim3 blk(256, 1, 1);
    const size_t sQK = (size_t)T_SZ * D_SZ;
    const size_t sS  = (size_t)T_SZ * T_SZ;

    // Round inputs to tf32 once (makes in-GEMM truncation exact)
    {
        const int n4x = (B_SZ * T_SZ * D_SZ) / 4;
        cvt_tf32<<<(n4x + 255) / 256, 256>>>((const float4*)Xin, (float4*)X, n4x);
        const int n4w = (D_SZ * D_SZ) / 4;
        cvt_tf32<<<(n4w + 255) / 256, 256>>>((const float4*)Wq, (float4*)W, n4w);
        cvt_tf32<<<(n4w + 255) / 256, 256>>>((const float4*)Wk,
                                             (float4*)(W + D_SZ * D_SZ), n4w);
        cvt_tf32<<<(n4w + 255) / 256, 256>>>((const float4*)Wv,
                                             (float4*)(W + 2 * D_SZ * D_SZ), n4w);
    }

    // QKV projections (outputs rounded to tf32 in epilogue)
    gemm_tf32<false, false, false, true>
        <<<dim3(D_SZ / BN, (B_SZ * T_SZ) / BM, 1), blk, SMEM_NN>>>(
            X, W, Q, D_SZ, D_SZ, 0, 0, 0);
    gemm_tf32<false, false, false, true>
        <<<dim3(D_SZ / BN, (B_SZ * T_SZ) / BM, 1), blk, SMEM_NN>>>(
            X, W + D_SZ * D_SZ, K, D_SZ, D_SZ, 0, 0, 0);
    gemm_tf32<false, false, false, true>
        <<<dim3(D_SZ / BN, (B_SZ * T_SZ) / BM, 1), blk, SMEM_NN>>>(
            X, W + 2 * D_SZ * D_SZ, V, D_SZ, D_SZ, 0, 0, 0);

    // Scores: S = Q K^T (causal blocks skipped)
    gemm_tf32<true, true, false, false>
        <<<dim3(T_SZ / BN, T_SZ / BM, B_SZ), blk, SMEM_NT>>>(
            Q, K, S, T_SZ, D_SZ, sQK, sQK, sS);

    // Softmax (scale + mask fused, P rounded to tf32)
    softmax_causal<<<B_SZ * T_SZ, 256>>>(S, P);

    // Output: O = P V (K-loop causally limited)
    gemm_tf32<false, false, true, false>
        <<<dim3(D_SZ / BN, T_SZ / BM, B_SZ), blk, SMEM_NN>>>(
            P, V, out, D_SZ, T_SZ, sS, sQK, sQK);
}

// round 6
// speedup vs baseline: 1.1746x; 1.0078x over previous
#include <cuda_runtime.h>
#include <cuda_bf16.h>
#include <cstdint>
#include <mma.h>

using namespace nvcuda;

#define B_SZ 4
#define T_SZ 2048
#define D_SZ 1024
__device__ __constant__ float kScale = 0.03125f; // 1/sqrt(1024)

// Scratch (device globals: allocation-free per harness rules)
__device__ float g_X[B_SZ * T_SZ * D_SZ];       // X rounded to tf32
__device__ float g_W[3 * D_SZ * D_SZ];          // Wq|Wk|Wv rounded to tf32
__device__ float g_Q[B_SZ * T_SZ * D_SZ];
__device__ float g_K[B_SZ * T_SZ * D_SZ];
__device__ float g_V[B_SZ * T_SZ * D_SZ];
__device__ float g_S[B_SZ * T_SZ * T_SZ];
__device__ float g_P[B_SZ * T_SZ * T_SZ];

// ---------------------------------------------------------------------------
// cp.async helpers
// ---------------------------------------------------------------------------
__device__ __forceinline__ void cp_async16(void* smem_dst, const void* gsrc) {
    unsigned s = (unsigned)__cvta_generic_to_shared(smem_dst);
    asm volatile("cp.async.cg.shared.global [%0], [%1], 16;" :: "r"(s), "l"(gsrc));
}
__device__ __forceinline__ void cp_commit() {
    asm volatile("cp.async.commit_group;");
}
template <int N>
__device__ __forceinline__ void cp_wait() {
    asm volatile("cp.async.wait_group %0;" :: "n"(N));
}

// ---------------------------------------------------------------------------
// TF32 WMMA GEMM, 3-stage cp.async ring, ONE __syncthreads per k-tile.
// Block 128x128x32, 8 warps (4x2), warp tile 32x64.
// Operands PRE-ROUNDED to tf32 -> HMMA truncation exact.
// TRANSB: B=[N,K] used as B^T. CSKIP: skip causal-upper blocks.
// KLIM: K-loop limited to (bm+1)*BM. CVT: round C to tf32 on store.
// ---------------------------------------------------------------------------
constexpr int BM = 128, BN = 128, BK = 32;
constexpr int AS_STR = BK + 4;  // 36
constexpr int NSTAGE = 3;

// Per-stage float counts and host-side smem byte sizes
constexpr int STAGE_NN = BM * AS_STR + BK * (BN + 4);   // 8832 floats
constexpr int STAGE_NT = BM * AS_STR + BN * (BK + 4);   // 9216 floats
constexpr int SMEM_NN = NSTAGE * STAGE_NN * 4;          // 105984 B
constexpr int SMEM_NT = NSTAGE * STAGE_NT * 4;          // 110592 B

template <bool TRANSB, bool CSKIP, bool KLIM, bool CVT>
__global__ __launch_bounds__(256) void gemm_tf32(
    const float* __restrict__ A, const float* __restrict__ Bm,
    float* __restrict__ C, int N, int K,
    size_t sA, size_t sB, size_t sC)
{
    const int bm = blockIdx.y, bn = blockIdx.x, bz = blockIdx.z;
    if (CSKIP && bn > bm) return;
    A  += (size_t)bz * sA;
    Bm += (size_t)bz * sB;
    C  += (size_t)bz * sC;

    constexpr int BROWS = TRANSB ? BN : BK;
    constexpr int BSTR  = TRANSB ? (BK + 4) : (BN + 4);
    constexpr int STAGE = BM * AS_STR + BROWS * BSTR;

    extern __shared__ float sm[];

    const int tid  = threadIdx.x;
    const int warp = tid >> 5;
    const int wrow = (warp & 3) * 32;
    const int wcol = (warp >> 2) * 64;

    wmma::fragment<wmma::accumulator, 16, 16, 8, float> acc[2][4];
    #pragma unroll
    for (int i = 0; i < 2; i++)
        #pragma unroll
        for (int j = 0; j < 4; j++) wmma::fill_fragment(acc[i][j], 0.0f);

    const int nk = KLIM ? ((bm + 1) * BM) / BK : K / BK;

    const int ar = tid >> 3,  ac = (tid & 7) * 4;   // 32-wide rows
    const int br = tid >> 5,  bc = (tid & 31) * 4;  // 128-wide rows

    auto load_stage = [&](int kt, int st) {
        const int k0 = kt * BK;
        float* As = sm + st * STAGE;
        float* Bs = As + BM * AS_STR;
        #pragma unroll
        for (int p = 0; p < 4; p++)
            cp_async16(As + (p * 32 + ar) * AS_STR + ac,
                       A + (size_t)(bm * BM + p * 32 + ar) * K + k0 + ac);
        if (TRANSB) {
            #pragma unroll
            for (int p = 0; p < 4; p++)
                cp_async16(Bs + (p * 32 + ar) * BSTR + ac,
                           Bm + (size_t)(bn * BN + p * 32 + ar) * K + k0 + ac);
        } else {
            #pragma unroll
            for (int p = 0; p < 4; p++)
                cp_async16(Bs + (p * 8 + br) * BSTR + bc,
                           Bm + (size_t)(k0 + p * 8 + br) * N + bn * BN + bc);
        }
        cp_commit();
    };

    // Prologue: fill first NSTAGE-1 slots
    load_stage(0, 0);
    if (nk > 1) load_stage(1, 1);

    for (int kt = 0; kt < nk; kt++) {
        // Stage kt ready when <= (#outstanding newer groups) remain
        if (kt + 1 < nk) cp_wait<1>();
        else             cp_wait<0>();
        __syncthreads();

        // Prefetch stage kt+2 into the slot retired at iteration kt-1
        if (kt + 2 < nk) load_stage(kt + 2, (kt + 2) % NSTAGE);

        const float* As = sm + (kt % NSTAGE) * STAGE;
        const float* Bs = As + BM * AS_STR;

        #pragma unroll
        for (int kk = 0; kk < BK / 8; kk++) {
            wmma::fragment<wmma::matrix_a, 16, 16, 8, wmma::precision::tf32,
                           wmma::row_major> af[2];
            #pragma unroll
            for (int i = 0; i < 2; i++)
                wmma::load_matrix_sync(af[i], As + (wrow + i * 16) * AS_STR + kk * 8,
                                       AS_STR);
            if constexpr (TRANSB) {
                wmma::fragment<wmma::matrix_b, 16, 16, 8, wmma::precision::tf32,
                               wmma::col_major> bf[4];
                #pragma unroll
                for (int j = 0; j < 4; j++)
                    wmma::load_matrix_sync(bf[j], Bs + (wcol + j * 16) * BSTR + kk * 8,
                                           BSTR);
                #pragma unroll
                for (int i = 0; i < 2; i++)
                    #pragma unroll
                    for (int j = 0; j < 4; j++)
                        wmma::mma_sync(acc[i][j], af[i], bf[j], acc[i][j]);
            } else {
                wmma::fragment<wmma::matrix_b, 16, 16, 8, wmma::precision::tf32,
                               wmma::row_major> bf[4];
                #pragma unroll
                for (int j = 0; j < 4; j++)
                    wmma::load_matrix_sync(bf[j], Bs + (kk * 8) * BSTR + wcol + j * 16,
                                           BSTR);
                #pragma unroll
                for (int i = 0; i < 2; i++)
                    #pragma unroll
                    for (int j = 0; j < 4; j++)
                        wmma::mma_sync(acc[i][j], af[i], bf[j], acc[i][j]);
            }
        }
    }

    #pragma unroll
    for (int i = 0; i < 2; i++)
        #pragma unroll
        for (int j = 0; j < 4; j++) {
            if (CVT) {
                #pragma unroll
                for (int e = 0; e < acc[i][j].num_elements; e++)
                    acc[i][j].x[e] = wmma::__float_to_tf32(acc[i][j].x[e]);
            }
            wmma::store_matrix_sync(
                &C[(size_t)(bm * BM + wrow + i * 16) * N + bn * BN + wcol + j * 16],
                acc[i][j], N, wmma::mem_row_major);
        }
}

// ---------------------------------------------------------------------------
// Elementwise round-to-tf32 (float4 vectorized)
// ---------------------------------------------------------------------------
__global__ void cvt_tf32(const float4* __restrict__ in, float4* __restrict__ out,
                         int n4)
{
    const int i = blockIdx.x * blockDim.x + threadIdx.x;
    if (i < n4) {
        float4 v = in[i];
        v.x = wmma::__float_to_tf32(v.x);
        v.y = wmma::__float_to_tf32(v.y);
        v.z = wmma::__float_to_tf32(v.z);
        v.w = wmma::__float_to_tf32(v.w);
        out[i] = v;
    }
}

// ---------------------------------------------------------------------------
// Row softmax: causal mask + scale fused, output rounded to tf32.
// ---------------------------------------------------------------------------
__global__ __launch_bounds__(256) void softmax_causal(
    const float* __restrict__ S, float* __restrict__ P)
{
    const int row = blockIdx.x;
    const int t   = row & (T_SZ - 1);
    const size_t base = (size_t)row * T_SZ;
    const int tid = threadIdx.x;

    float e[8];
    float m = -1e30f;
    #pragma unroll
    for (int i = 0; i < 8; i++) {
        const int j = tid + i * 256;
        const float v = (j <= t) ? S[base + j] * kScale : -1e30f;
        e[i] = v;
        m = fmaxf(m, v);
    }

    __shared__ float shm[8], shs[8];
    #pragma unroll
    for (int o = 16; o; o >>= 1) m = fmaxf(m, __shfl_xor_sync(0xffffffffu, m, o));
    if ((tid & 31) == 0) shm[tid >> 5] = m;
    __syncthreads();
    float mfin = shm[0];
    #pragma unroll
    for (int i = 1; i < 8; i++) mfin = fmaxf(mfin, shm[i]);

    float s = 0.0f;
    #pragma unroll
    for (int i = 0; i < 8; i++) {
        e[i] = __expf(e[i] - mfin);
        s += e[i];
    }
    #pragma unroll
    for (int o = 16; o; o >>= 1) s += __shfl_xor_sync(0xffffffffu, s, o);
    if ((tid & 31) == 0) shs[tid >> 5] = s;
    __syncthreads();
    float sfin = 0.0f;
    #pragma unroll
    for (int i = 0; i < 8; i++) sfin += shs[i];

    const float inv = 1.0f / sfin;
    #pragma unroll
    for (int i = 0; i < 8; i++)
        P[base + tid + i * 256] = wmma::__float_to_tf32(e[i] * inv);
}

// ---------------------------------------------------------------------------
extern "C" void kernel_launch(void* const* d_in, const int* in_sizes, int n_in,
                              void* d_out, int out_size)
{
    (void)in_sizes; (void)n_in; (void)out_size;
    const float* Xin = (const float*)d_in[0];
    const float* Wq  = (const float*)d_in[1];
    const float* Wk  = (const float*)d_in[2];
    const float* Wv  = (const float*)d_in[3];
    float* out = (float*)d_out;

    float *X, *W, *Q, *K, *V, *S, *P;
    cudaGetSymbolAddress((void**)&X, g_X);
    cudaGetSymbolAddress((void**)&W, g_W);
    cudaGetSymbolAddress((void**)&Q, g_Q);
    cudaGetSymbolAddress((void**)&K, g_K);
    cudaGetSymbolAddress((void**)&V, g_V);
    cudaGetSymbolAddress((void**)&S, g_S);
    cudaGetSymbolAddress((void**)&P, g_P);

    cudaFuncSetAttribute(gemm_tf32<false, false, false, true>,
                         cudaFuncAttributeMaxDynamicSharedMemorySize, SMEM_NN);
    cudaFuncSetAttribute(gemm_tf32<true, true, false, false>,
                         cudaFuncAttributeMaxDynamicSharedMemorySize, SMEM_NT);
    cudaFuncSetAttribute(gemm_tf32<false, false, true, false>,
                         cudaFuncAttributeMaxDynamicSharedMemorySize, SMEM_NN);

    const dim3 blk(256, 1, 1);
    const size_t sQK = (size_t)T_SZ * D_SZ;
    const size_t sS  = (size_t)T_SZ * T_SZ;

    // Round inputs to tf32 once (makes in-GEMM truncation exact)
    {
        const int n4x = (B_SZ * T_SZ * D_SZ) / 4;
        cvt_tf32<<<(n4x + 255) / 256, 256>>>((const float4*)Xin, (float4*)X, n4x);
        const int n4w = (D_SZ * D_SZ) / 4;
        cvt_tf32<<<(n4w + 255) / 256, 256>>>((const float4*)Wq, (float4*)W, n4w);
        cvt_tf32<<<(n4w + 255) / 256, 256>>>((const float4*)Wk,
                                             (float4*)(W + D_SZ * D_SZ), n4w);
        cvt_tf32<<<(n4w + 255) / 256, 256>>>((const float4*)Wv,
                                             (float4*)(W + 2 * D_SZ * D_SZ), n4w);
    }

    // QKV projections (outputs rounded to tf32 in epilogue)
    gemm_tf32<false, false, false, true>
        <<<dim3(D_SZ / BN, (B_SZ * T_SZ) / BM, 1), blk, SMEM_NN>>>(
            X, W, Q, D_SZ, D_SZ, 0, 0, 0);
    gemm_tf32<false, false, false, true>
        <<<dim3(D_SZ / BN, (B_SZ * T_SZ) / BM, 1), blk, SMEM_NN>>>(
            X, W + D_SZ * D_SZ, K, D_SZ, D_SZ, 0, 0, 0);
    gemm_tf32<false, false, false, true>
        <<<dim3(D_SZ / BN, (B_SZ * T_SZ) / BM, 1), blk, SMEM_NN>>>(
            X, W + 2 * D_SZ * D_SZ, V, D_SZ, D_SZ, 0, 0, 0);

    // Scores: S = Q K^T (causal blocks skipped)
    gemm_tf32<true, true, false, false>
        <<<dim3(T_SZ / BN, T_SZ / BM, B_SZ), blk, SMEM_NT>>>(
            Q, K, S, T_SZ, D_SZ, sQK, sQK, sS);

    // Softmax (scale + mask fused, P rounded to tf32)
    softmax_causal<<<B_SZ * T_SZ, 256>>>(S, P);

    // Output: O = P V (K-loop causally limited)
    gemm_tf32<false, false, true, false>
        <<<dim3(D_SZ / BN, T_SZ / BM, B_SZ), blk, SMEM_NN>>>(
            P, V, out, D_SZ, T_SZ, sS, sQK, sQK);
}

// round 7
// speedup vs baseline: 1.1756x; 1.0009x over previous
#include <cuda_runtime.h>
#include <cuda_bf16.h>
#include <cstdint>
#include <mma.h>

using namespace nvcuda;

#define B_SZ 4
#define T_SZ 2048
#define D_SZ 1024
__device__ __constant__ float kScale = 0.03125f; // 1/sqrt(1024)

// Scratch (device globals: allocation-free per harness rules)
__device__ float g_X[B_SZ * T_SZ * D_SZ];       // X rounded to tf32
__device__ float g_W[3 * D_SZ * D_SZ];          // Wq|Wk|Wv rounded to tf32
__device__ float g_Q[B_SZ * T_SZ * D_SZ];
__device__ float g_K[B_SZ * T_SZ * D_SZ];
__device__ float g_V[B_SZ * T_SZ * D_SZ];
__device__ float g_S[B_SZ * T_SZ * T_SZ];
__device__ float g_P[B_SZ * T_SZ * T_SZ];

// ---------------------------------------------------------------------------
// cp.async helpers
// ---------------------------------------------------------------------------
__device__ __forceinline__ void cp_async16(void* smem_dst, const void* gsrc) {
    unsigned s = (unsigned)__cvta_generic_to_shared(smem_dst);
    asm volatile("cp.async.cg.shared.global [%0], [%1], 16;" :: "r"(s), "l"(gsrc));
}
__device__ __forceinline__ void cp_commit() {
    asm volatile("cp.async.commit_group;");
}
template <int N>
__device__ __forceinline__ void cp_wait() {
    asm volatile("cp.async.wait_group %0;" :: "n"(N));
}

// ---------------------------------------------------------------------------
// TF32 WMMA GEMM, 3-stage cp.async ring, ONE __syncthreads per k-tile.
// Block 128x128x32, 8 warps (4x2), warp tile 32x64.
// Operands PRE-ROUNDED to tf32 -> HMMA truncation exact.
// TRANSB: B=[N,K] used as B^T. CSKIP: skip causal-upper blocks.
// KLIM: K-loop limited to (bm+1)*BM. CVT: round C to tf32 on store.
// ---------------------------------------------------------------------------
constexpr int BM = 128, BN = 128, BK = 32;
constexpr int AS_STR = BK + 4;  // 36
constexpr int NSTAGE = 3;

// Per-stage float counts and host-side smem byte sizes
constexpr int STAGE_NN = BM * AS_STR + BK * (BN + 4);   // 8832 floats
constexpr int STAGE_NT = BM * AS_STR + BN * (BK + 4);   // 9216 floats
constexpr int SMEM_NN = NSTAGE * STAGE_NN * 4;          // 105984 B
constexpr int SMEM_NT = NSTAGE * STAGE_NT * 4;          // 110592 B

template <bool TRANSB, bool CSKIP, bool KLIM, bool CVT>
__global__ __launch_bounds__(256) void gemm_tf32(
    const float* __restrict__ A, const float* __restrict__ Bm,
    float* __restrict__ C, int N, int K,
    size_t sA, size_t sB, size_t sC)
{
    const int bm = blockIdx.y, bn = blockIdx.x, bz = blockIdx.z;
    if (CSKIP && bn > bm) return;
    A  += (size_t)bz * sA;
    Bm += (size_t)bz * sB;
    C  += (size_t)bz * sC;

    constexpr int BROWS = TRANSB ? BN : BK;
    constexpr int BSTR  = TRANSB ? (BK + 4) : (BN + 4);
    constexpr int STAGE = BM * AS_STR + BROWS * BSTR;

    extern __shared__ float sm[];

    const int tid  = threadIdx.x;
    const int warp = tid >> 5;
    const int wrow = (warp & 3) * 32;
    const int wcol = (warp >> 2) * 64;

    wmma::fragment<wmma::accumulator, 16, 16, 8, float> acc[2][4];
    #pragma unroll
    for (int i = 0; i < 2; i++)
        #pragma unroll
        for (int j = 0; j < 4; j++) wmma::fill_fragment(acc[i][j], 0.0f);

    const int nk = KLIM ? ((bm + 1) * BM) / BK : K / BK;

    const int ar = tid >> 3,  ac = (tid & 7) * 4;   // 32-wide rows
    const int br = tid >> 5,  bc = (tid & 31) * 4;  // 128-wide rows

    auto load_stage = [&](int kt, int st) {
        const int k0 = kt * BK;
        float* As = sm + st * STAGE;
        float* Bs = As + BM * AS_STR;
        #pragma unroll
        for (int p = 0; p < 4; p++)
            cp_async16(As + (p * 32 + ar) * AS_STR + ac,
                       A + (size_t)(bm * BM + p * 32 + ar) * K + k0 + ac);
        if (TRANSB) {
            #pragma unroll
            for (int p = 0; p < 4; p++)
                cp_async16(Bs + (p * 32 + ar) * BSTR + ac,
                           Bm + (size_t)(bn * BN + p * 32 + ar) * K + k0 + ac);
        } else {
            #pragma unroll
            for (int p = 0; p < 4; p++)
                cp_async16(Bs + (p * 8 + br) * BSTR + bc,
                           Bm + (size_t)(k0 + p * 8 + br) * N + bn * BN + bc);
        }
        cp_commit();
    };

    // Prologue: fill first NSTAGE-1 slots
    load_stage(0, 0);
    if (nk > 1) load_stage(1, 1);

    for (int kt = 0; kt < nk; kt++) {
        // Stage kt ready when <= (#outstanding newer groups) remain
        if (kt + 1 < nk) cp_wait<1>();
        else             cp_wait<0>();
        __syncthreads();

        // Prefetch stage kt+2 into the slot retired at iteration kt-1
        if (kt + 2 < nk) load_stage(kt + 2, (kt + 2) % NSTAGE);

        const float* As = sm + (kt % NSTAGE) * STAGE;
        const float* Bs = As + BM * AS_STR;

        #pragma unroll
        for (int kk = 0; kk < BK / 8; kk++) {
            wmma::fragment<wmma::matrix_a, 16, 16, 8, wmma::precision::tf32,
                           wmma::row_major> af[2];
            #pragma unroll
            for (int i = 0; i < 2; i++)
                wmma::load_matrix_sync(af[i], As + (wrow + i * 16) * AS_STR + kk * 8,
                                       AS_STR);
            if constexpr (TRANSB) {
                wmma::fragment<wmma::matrix_b, 16, 16, 8, wmma::precision::tf32,
                               wmma::col_major> bf[4];
                #pragma unroll
                for (int j = 0; j < 4; j++)
                    wmma::load_matrix_sync(bf[j], Bs + (wcol + j * 16) * BSTR + kk * 8,
                                           BSTR);
                #pragma unroll
                for (int i = 0; i < 2; i++)
                    #pragma unroll
                    for (int j = 0; j < 4; j++)
                        wmma::mma_sync(acc[i][j], af[i], bf[j], acc[i][j]);
            } else {
                wmma::fragment<wmma::matrix_b, 16, 16, 8, wmma::precision::tf32,
                               wmma::row_major> bf[4];
                #pragma unroll
                for (int j = 0; j < 4; j++)
                    wmma::load_matrix_sync(bf[j], Bs + (kk * 8) * BSTR + wcol + j * 16,
                                           BSTR);
                #pragma unroll
                for (int i = 0; i < 2; i++)
                    #pragma unroll
                    for (int j = 0; j < 4; j++)
                        wmma::mma_sync(acc[i][j], af[i], bf[j], acc[i][j]);
            }
        }
    }

    #pragma unroll
    for (int i = 0; i < 2; i++)
        #pragma unroll
        for (int j = 0; j < 4; j++) {
            if (CVT) {
                #pragma unroll
                for (int e = 0; e < acc[i][j].num_elements; e++)
                    acc[i][j].x[e] = wmma::__float_to_tf32(acc[i][j].x[e]);
            }
            wmma::store_matrix_sync(
                &C[(size_t)(bm * BM + wrow + i * 16) * N + bn * BN + wcol + j * 16],
                acc[i][j], N, wmma::mem_row_major);
        }
}

// ---------------------------------------------------------------------------
// Elementwise round-to-tf32 (float4 vectorized)
// ---------------------------------------------------------------------------
__global__ void cvt_tf32(const float4* __restrict__ in, float4* __restrict__ out,
                         int n4)
{
    const int i = blockIdx.x * blockDim.x + threadIdx.x;
    if (i < n4) {
        float4 v = in[i];
        v.x = wmma::__float_to_tf32(v.x);
        v.y = wmma::__float_to_tf32(v.y);
        v.z = wmma::__float_to_tf32(v.z);
        v.w = wmma::__float_to_tf32(v.w);
        out[i] = v;
    }
}

// ---------------------------------------------------------------------------
// Row softmax: causal mask + scale fused, output rounded to tf32.
// ---------------------------------------------------------------------------
__global__ __launch_bounds__(256) void softmax_causal(
    const float* __restrict__ S, float* __restrict__ P)
{
    const int row = blockIdx.x;
    const int t   = row & (T_SZ - 1);
    const size_t base = (size_t)row * T_SZ;
    const int tid = threadIdx.x;

    float e[8];
    float m = -1e30f;
    #pragma unroll
    for (int i = 0; i < 8; i++) {
        const int j = tid + i * 256;
        const float v = (j <= t) ? S[base + j] * kScale : -1e30f;
        e[i] = v;
        m = fmaxf(m, v);
    }

    __shared__ float shm[8], shs[8];
    #pragma unroll
    for (int o = 16; o; o >>= 1) m = fmaxf(m, __shfl_xor_sync(0xffffffffu, m, o));
    if ((tid & 31) == 0) shm[tid >> 5] = m;
    __syncthreads();
    float mfin = shm[0];
    #pragma unroll
    for (int i = 1; i < 8; i++) mfin = fmaxf(mfin, shm[i]);

    float s = 0.0f;
    #pragma unroll
    for (int i = 0; i < 8; i++) {
        e[i] = __expf(e[i] - mfin);
        s += e[i];
    }
    #pragma unroll
    for (int o = 16; o; o >>= 1) s += __shfl_xor_sync(0xffffffffu, s, o);
    if ((tid & 31) == 0) shs[tid >> 5] = s;
    __syncthreads();
    float sfin = 0.0f;
    #pragma unroll
    for (int i = 0; i < 8; i++) sfin += shs[i];

    const float inv = 1.0f / sfin;
    #pragma unroll
    for (int i = 0; i < 8; i++)
        P[base + tid + i * 256] = wmma::__float_to_tf32(e[i] * inv);
}

// ---------------------------------------------------------------------------
extern "C" void kernel_launch(void* const* d_in, const int* in_sizes, int n_in,
                              void* d_out, int out_size)
{
    (void)in_sizes; (void)n_in; (void)out_size;
    const float* Xin = (const float*)d_in[0];
    const float* Wq  = (const float*)d_in[1];
    const float* Wk  = (const float*)d_in[2];
    const float* Wv  = (const float*)d_in[3];
    float* out = (float*)d_out;

    float *X, *W, *Q, *K, *V, *S, *P;
    cudaGetSymbolAddress((void**)&X, g_X);
    cudaGetSymbolAddress((void**)&W, g_W);
    cudaGetSymbolAddress((void**)&Q, g_Q);
    cudaGetSymbolAddress((void**)&K, g_K);
    cudaGetSymbolAddress((void**)&V, g_V);
    cudaGetSymbolAddress((void**)&S, g_S);
    cudaGetSymbolAddress((void**)&P, g_P);

    cudaFuncSetAttribute(gemm_tf32<false, false, false, true>,
                         cudaFuncAttributeMaxDynamicSharedMemorySize, SMEM_NN);
    cudaFuncSetAttribute(gemm_tf32<true, true, false, false>,
                         cudaFuncAttributeMaxDynamicSharedMemorySize, SMEM_NT);
    cudaFuncSetAttribute(gemm_tf32<false, false, true, false>,
                         cudaFuncAttributeMaxDynamicSharedMemorySize, SMEM_NN);

    const dim3 blk(256, 1, 1);
    const size_t sQK = (size_t)T_SZ * D_SZ;
    const size_t sS  = (size_t)T_SZ * T_SZ;

    // Round inputs to tf32 once (makes in-GEMM truncation exact)
    {
        const int n4x = (B_SZ * T_SZ * D_SZ) / 4;
        cvt_tf32<<<(n4x + 255) / 256, 256>>>((const float4*)Xin, (float4*)X, n4x);
        const int n4w = (D_SZ * D_SZ) / 4;
        cvt_tf32<<<(n4w + 255) / 256, 256>>>((const float4*)Wq, (float4*)W, n4w);
        cvt_tf32<<<(n4w + 255) / 256, 256>>>((const float4*)Wk,
                                             (float4*)(W + D_SZ * D_SZ), n4w);
        cvt_tf32<<<(n4w + 255) / 256, 256>>>((const float4*)Wv,
                                             (float4*)(W + 2 * D_SZ * D_SZ), n4w);
    }

    // QKV projections (outputs rounded to tf32 in epilogue)
    gemm_tf32<false, false, false, true>
        <<<dim3(D_SZ / BN, (B_SZ * T_SZ) / BM, 1), blk, SMEM_NN>>>(
            X, W, Q, D_SZ, D_SZ, 0, 0, 0);
    gemm_tf32<false, false, false, true>
        <<<dim3(D_SZ / BN, (B_SZ * T_SZ) / BM, 1), blk, SMEM_NN>>>(
            X, W + D_SZ * D_SZ, K, D_SZ, D_SZ, 0, 0, 0);
    gemm_tf32<false, false, false, true>
        <<<dim3(D_SZ / BN, (B_SZ * T_SZ) / BM, 1), blk, SMEM_NN>>>(
            X, W + 2 * D_SZ * D_SZ, V, D_SZ, D_SZ, 0, 0, 0);

    // Scores: S = Q K^T (causal blocks skipped)
    gemm_tf32<true, true, false, false>
        <<<dim3(T_SZ / BN, T_SZ / BM, B_SZ), blk, SMEM_NT>>>(
            Q, K, S, T_SZ, D_SZ, sQK, sQK, sS);

    // Softmax (scale + mask fused, P rounded to tf32)
    softmax_causal<<<B_SZ * T_SZ, 256>>>(S, P);

    // Output: O = P V (K-loop causally limited)
    gemm_tf32<false, false, true, false>
        <<<dim3(D_SZ / BN, T_SZ / BM, B_SZ), blk, SMEM_NN>>>(
            P, V, out, D_SZ, T_SZ, sS, sQK, sQK);
}

// round 8
// speedup vs baseline: 1.1757x; 1.0000x over previous
#include <cuda_runtime.h>
#include <cuda_bf16.h>
#include <cstdint>
#include <mma.h>

using namespace nvcuda;

#define B_SZ 4
#define T_SZ 2048
#define D_SZ 1024
__device__ __constant__ float kScale = 0.03125f; // 1/sqrt(1024)

// Scratch (device globals: allocation-free per harness rules)
__device__ float g_X[B_SZ * T_SZ * D_SZ];       // X rounded to tf32
__device__ float g_W[3 * D_SZ * D_SZ];          // Wq|Wk|Wv rounded to tf32
__device__ float g_Q[B_SZ * T_SZ * D_SZ];
__device__ float g_K[B_SZ * T_SZ * D_SZ];
__device__ float g_V[B_SZ * T_SZ * D_SZ];
__device__ float g_S[B_SZ * T_SZ * T_SZ];
__device__ float g_P[B_SZ * T_SZ * T_SZ];

// ---------------------------------------------------------------------------
// cp.async helpers
// ---------------------------------------------------------------------------
__device__ __forceinline__ void cp_async16(void* smem_dst, const void* gsrc) {
    unsigned s = (unsigned)__cvta_generic_to_shared(smem_dst);
    asm volatile("cp.async.cg.shared.global [%0], [%1], 16;" :: "r"(s), "l"(gsrc));
}
__device__ __forceinline__ void cp_commit() {
    asm volatile("cp.async.commit_group;");
}
template <int N>
__device__ __forceinline__ void cp_wait() {
    asm volatile("cp.async.wait_group %0;" :: "n"(N));
}

// ---------------------------------------------------------------------------
// TF32 WMMA GEMM, 3-stage cp.async ring, ONE __syncthreads per k-tile.
// Block 128x128x32, 8 warps (4x2), warp tile 32x64.
// Operands PRE-ROUNDED to tf32 -> HMMA truncation exact.
// TRANSB: B=[N,K] used as B^T. CSKIP: skip causal-upper blocks.
// KLIM: K-loop limited to (bm+1)*BM. CVT: round C to tf32 on store.
// ---------------------------------------------------------------------------
constexpr int BM = 128, BN = 128, BK = 32;
constexpr int AS_STR = BK + 4;  // 36
constexpr int NSTAGE = 3;

// Per-stage float counts and host-side smem byte sizes
constexpr int STAGE_NN = BM * AS_STR + BK * (BN + 4);   // 8832 floats
constexpr int STAGE_NT = BM * AS_STR + BN * (BK + 4);   // 9216 floats
constexpr int SMEM_NN = NSTAGE * STAGE_NN * 4;          // 105984 B
constexpr int SMEM_NT = NSTAGE * STAGE_NT * 4;          // 110592 B

template <bool TRANSB, bool CSKIP, bool KLIM, bool CVT>
__global__ __launch_bounds__(256) void gemm_tf32(
    const float* __restrict__ A, const float* __restrict__ Bm,
    float* __restrict__ C, int N, int K,
    size_t sA, size_t sB, size_t sC)
{
    const int bm = blockIdx.y, bn = blockIdx.x, bz = blockIdx.z;
    if (CSKIP && bn > bm) return;
    A  += (size_t)bz * sA;
    Bm += (size_t)bz * sB;
    C  += (size_t)bz * sC;

    constexpr int BROWS = TRANSB ? BN : BK;
    constexpr int BSTR  = TRANSB ? (BK + 4) : (BN + 4);
    constexpr int STAGE = BM * AS_STR + BROWS * BSTR;

    extern __shared__ float sm[];

    const int tid  = threadIdx.x;
    const int warp = tid >> 5;
    const int wrow = (warp & 3) * 32;
    const int wcol = (warp >> 2) * 64;

    wmma::fragment<wmma::accumulator, 16, 16, 8, float> acc[2][4];
    #pragma unroll
    for (int i = 0; i < 2; i++)
        #pragma unroll
        for (int j = 0; j < 4; j++) wmma::fill_fragment(acc[i][j], 0.0f);

    const int nk = KLIM ? ((bm + 1) * BM) / BK : K / BK;

    const int ar = tid >> 3,  ac = (tid & 7) * 4;   // 32-wide rows
    const int br = tid >> 5,  bc = (tid & 31) * 4;  // 128-wide rows

    auto load_stage = [&](int kt, int st) {
        const int k0 = kt * BK;
        float* As = sm + st * STAGE;
        float* Bs = As + BM * AS_STR;
        #pragma unroll
        for (int p = 0; p < 4; p++)
            cp_async16(As + (p * 32 + ar) * AS_STR + ac,
                       A + (size_t)(bm * BM + p * 32 + ar) * K + k0 + ac);
        if (TRANSB) {
            #pragma unroll
            for (int p = 0; p < 4; p++)
                cp_async16(Bs + (p * 32 + ar) * BSTR + ac,
                           Bm + (size_t)(bn * BN + p * 32 + ar) * K + k0 + ac);
        } else {
            #pragma unroll
            for (int p = 0; p < 4; p++)
                cp_async16(Bs + (p * 8 + br) * BSTR + bc,
                           Bm + (size_t)(k0 + p * 8 + br) * N + bn * BN + bc);
        }
        cp_commit();
    };

    // Prologue: fill first NSTAGE-1 slots
    load_stage(0, 0);
    if (nk > 1) load_stage(1, 1);

    for (int kt = 0; kt < nk; kt++) {
        // Stage kt ready when <= (#outstanding newer groups) remain
        if (kt + 1 < nk) cp_wait<1>();
        else             cp_wait<0>();
        __syncthreads();

        // Prefetch stage kt+2 into the slot retired at iteration kt-1
        if (kt + 2 < nk) load_stage(kt + 2, (kt + 2) % NSTAGE);

        const float* As = sm + (kt % NSTAGE) * STAGE;
        const float* Bs = As + BM * AS_STR;

        #pragma unroll
        for (int kk = 0; kk < BK / 8; kk++) {
            wmma::fragment<wmma::matrix_a, 16, 16, 8, wmma::precision::tf32,
                           wmma::row_major> af[2];
            #pragma unroll
            for (int i = 0; i < 2; i++)
                wmma::load_matrix_sync(af[i], As + (wrow + i * 16) * AS_STR + kk * 8,
                                       AS_STR);
            if constexpr (TRANSB) {
                wmma::fragment<wmma::matrix_b, 16, 16, 8, wmma::precision::tf32,
                               wmma::col_major> bf[4];
                #pragma unroll
                for (int j = 0; j < 4; j++)
                    wmma::load_matrix_sync(bf[j], Bs + (wcol + j * 16) * BSTR + kk * 8,
                                           BSTR);
                #pragma unroll
                for (int i = 0; i < 2; i++)
                    #pragma unroll
                    for (int j = 0; j < 4; j++)
                        wmma::mma_sync(acc[i][j], af[i], bf[j], acc[i][j]);
            } else {
                wmma::fragment<wmma::matrix_b, 16, 16, 8, wmma::precision::tf32,
                               wmma::row_major> bf[4];
                #pragma unroll
                for (int j = 0; j < 4; j++)
                    wmma::load_matrix_sync(bf[j], Bs + (kk * 8) * BSTR + wcol + j * 16,
                                           BSTR);
                #pragma unroll
                for (int i = 0; i < 2; i++)
                    #pragma unroll
                    for (int j = 0; j < 4; j++)
                        wmma::mma_sync(acc[i][j], af[i], bf[j], acc[i][j]);
            }
        }
    }

    #pragma unroll
    for (int i = 0; i < 2; i++)
        #pragma unroll
        for (int j = 0; j < 4; j++) {
            if (CVT) {
                #pragma unroll
                for (int e = 0; e < acc[i][j].num_elements; e++)
                    acc[i][j].x[e] = wmma::__float_to_tf32(acc[i][j].x[e]);
            }
            wmma::store_matrix_sync(
                &C[(size_t)(bm * BM + wrow + i * 16) * N + bn * BN + wcol + j * 16],
                acc[i][j], N, wmma::mem_row_major);
        }
}

// ---------------------------------------------------------------------------
// Elementwise round-to-tf32 (float4 vectorized)
// ---------------------------------------------------------------------------
__global__ void cvt_tf32(const float4* __restrict__ in, float4* __restrict__ out,
                         int n4)
{
    const int i = blockIdx.x * blockDim.x + threadIdx.x;
    if (i < n4) {
        float4 v = in[i];
        v.x = wmma::__float_to_tf32(v.x);
        v.y = wmma::__float_to_tf32(v.y);
        v.z = wmma::__float_to_tf32(v.z);
        v.w = wmma::__float_to_tf32(v.w);
        out[i] = v;
    }
}

// ---------------------------------------------------------------------------
// Row softmax: causal mask + scale fused, output rounded to tf32.
// ---------------------------------------------------------------------------
__global__ __launch_bounds__(256) void softmax_causal(
    const float* __restrict__ S, float* __restrict__ P)
{
    const int row = blockIdx.x;
    const int t   = row & (T_SZ - 1);
    const size_t base = (size_t)row * T_SZ;
    const int tid = threadIdx.x;

    float e[8];
    float m = -1e30f;
    #pragma unroll
    for (int i = 0; i < 8; i++) {
        const int j = tid + i * 256;
        const float v = (j <= t) ? S[base + j] * kScale : -1e30f;
        e[i] = v;
        m = fmaxf(m, v);
    }

    __shared__ float shm[8], shs[8];
    #pragma unroll
    for (int o = 16; o; o >>= 1) m = fmaxf(m, __shfl_xor_sync(0xffffffffu, m, o));
    if ((tid & 31) == 0) shm[tid >> 5] = m;
    __syncthreads();
    float mfin = shm[0];
    #pragma unroll
    for (int i = 1; i < 8; i++) mfin = fmaxf(mfin, shm[i]);

    float s = 0.0f;
    #pragma unroll
    for (int i = 0; i < 8; i++) {
        e[i] = __expf(e[i] - mfin);
        s += e[i];
    }
    #pragma unroll
    for (int o = 16; o; o >>= 1) s += __shfl_xor_sync(0xffffffffu, s, o);
    if ((tid & 31) == 0) shs[tid >> 5] = s;
    __syncthreads();
    float sfin = 0.0f;
    #pragma unroll
    for (int i = 0; i < 8; i++) sfin += shs[i];

    const float inv = 1.0f / sfin;
    #pragma unroll
    for (int i = 0; i < 8; i++)
        P[base + tid + i * 256] = wmma::__float_to_tf32(e[i] * inv);
}

// ---------------------------------------------------------------------------
extern "C" void kernel_launch(void* const* d_in, const int* in_sizes, int n_in,
                              void* d_out, int out_size)
{
    (void)in_sizes; (void)n_in; (void)out_size;
    const float* Xin = (const float*)d_in[0];
    const float* Wq  = (const float*)d_in[1];
    const float* Wk  = (const float*)d_in[2];
    const float* Wv  = (const float*)d_in[3];
    float* out = (float*)d_out;

    float *X, *W, *Q, *K, *V, *S, *P;
    cudaGetSymbolAddress((void**)&X, g_X);
    cudaGetSymbolAddress((void**)&W, g_W);
    cudaGetSymbolAddress((void**)&Q, g_Q);
    cudaGetSymbolAddress((void**)&K, g_K);
    cudaGetSymbolAddress((void**)&V, g_V);
    cudaGetSymbolAddress((void**)&S, g_S);
    cudaGetSymbolAddress((void**)&P, g_P);

    cudaFuncSetAttribute(gemm_tf32<false, false, false, true>,
                         cudaFuncAttributeMaxDynamicSharedMemorySize, SMEM_NN);
    cudaFuncSetAttribute(gemm_tf32<true, true, false, false>,
                         cudaFuncAttributeMaxDynamicSharedMemorySize, SMEM_NT);
    cudaFuncSetAttribute(gemm_tf32<false, false, true, false>,
                         cudaFuncAttributeMaxDynamicSharedMemorySize, SMEM_NN);

    const dim3 blk(256, 1, 1);
    const size_t sQK = (size_t)T_SZ * D_SZ;
    const size_t sS  = (size_t)T_SZ * T_SZ;

    // Round inputs to tf32 once (makes in-GEMM truncation exact)
    {
        const int n4x = (B_SZ * T_SZ * D_SZ) / 4;
        cvt_tf32<<<(n4x + 255) / 256, 256>>>((const float4*)Xin, (float4*)X, n4x);
        const int n4w = (D_SZ * D_SZ) / 4;
        cvt_tf32<<<(n4w + 255) / 256, 256>>>((const float4*)Wq, (float4*)W, n4w);
        cvt_tf32<<<(n4w + 255) / 256, 256>>>((const float4*)Wk,
                                             (float4*)(W + D_SZ * D_SZ), n4w);
        cvt_tf32<<<(n4w + 255) / 256, 256>>>((const float4*)Wv,
                                             (float4*)(W + 2 * D_SZ * D_SZ), n4w);
    }

    // QKV projections (outputs rounded to tf32 in epilogue)
    gemm_tf32<false, false, false, true>
        <<<dim3(D_SZ / BN, (B_SZ * T_SZ) / BM, 1), blk, SMEM_NN>>>(
            X, W, Q, D_SZ, D_SZ, 0, 0, 0);
    gemm_tf32<false, false, false, true>
        <<<dim3(D_SZ / BN, (B_SZ * T_SZ) / BM, 1), blk, SMEM_NN>>>(
            X, W + D_SZ * D_SZ, K, D_SZ, D_SZ, 0, 0, 0);
    gemm_tf32<false, false, false, true>
        <<<dim3(D_SZ / BN, (B_SZ * T_SZ) / BM, 1), blk, SMEM_NN>>>(
            X, W + 2 * D_SZ * D_SZ, V, D_SZ, D_SZ, 0, 0, 0);

    // Scores: S = Q K^T (causal blocks skipped)
    gemm_tf32<true, true, false, false>
        <<<dim3(T_SZ / BN, T_SZ / BM, B_SZ), blk, SMEM_NT>>>(
            Q, K, S, T_SZ, D_SZ, sQK, sQK, sS);

    // Softmax (scale + mask fused, P rounded to tf32)
    softmax_causal<<<B_SZ * T_SZ, 256>>>(S, P);

    // Output: O = P V (K-loop causally limited)
    gemm_tf32<false, false, true, false>
        <<<dim3(D_SZ / BN, T_SZ / BM, B_SZ), blk, SMEM_NN>>>(
            P, V, out, D_SZ, T_SZ, sS, sQK, sQK);
}